// round 13
// baseline (speedup 1.0000x reference)
#include <cuda_runtime.h>
#include <cuda_fp16.h>
#include <math.h>
#include <stdint.h>

#define NN 100000
#define NE 1600000
#define NF 133
#define HD 128
#define SA 36    // As row stride (floats): %32==4 -> conflict-free A frag reads
#define SB 136   // Bs row stride (floats): %32==8 -> conflict-free B frag reads

// ---- scratch (device globals) ----
__device__ __half d_gh[NN * HD];   // g = dis[n]*(h@W)[n], fp16 for gather bandwidth
__device__ float d_h[NN * HD];     // hidden activations between layers (fp32)
__device__ int   d_cnt[NN];
__device__ int   d_rowptr[NN + 1];
__device__ int   d_head[NN];
__device__ int   d_col[NE];
__device__ float d_dis[NN];

// ---------------- preprocessing ----------------

__global__ void zero_cnt_k() {
    int i = blockIdx.x * blockDim.x + threadIdx.x;
    if (i < NN) d_cnt[i] = 0;
}

__global__ void count_k(const int* __restrict__ ei) {
    int e = blockIdx.x * blockDim.x + threadIdx.x;
    if (e < NE) atomicAdd(&d_cnt[ei[NE + e]], 1);
}

__global__ void scan_k() {
    __shared__ int sums[1024];
    int t = threadIdx.x;
    const int CH = (NN + 1023) / 1024;
    int lo = t * CH;
    int hi = lo + CH; if (hi > NN) hi = NN;
    int s = 0;
    for (int i = lo; i < hi; i++) s += d_cnt[i];
    sums[t] = s;
    __syncthreads();
    for (int off = 1; off < 1024; off <<= 1) {
        int v = 0;
        if (t >= off) v = sums[t - off];
        __syncthreads();
        sums[t] += v;
        __syncthreads();
    }
    int run = sums[t] - s;
    for (int i = lo; i < hi; i++) {
        int c = d_cnt[i];
        d_rowptr[i] = run;
        d_head[i]   = run;
        d_dis[i]    = rsqrtf((float)c + 1.0f);
        run += c;
    }
    if (t == 1023) d_rowptr[NN] = run;
}

__global__ void fill_k(const int* __restrict__ ei) {
    int e = blockIdx.x * blockDim.x + threadIdx.x;
    if (e < NE) {
        int src = ei[e];
        int dst = ei[NE + e];
        int p = atomicAdd(&d_head[dst], 1);
        d_col[p] = src;
    }
}

// ---------------- per-layer GEMM (tf32 tensor cores) ----------------
// g_fp16 = dis[m] * (H @ W).  Block tile 128x128, 8 warps (4 M x 2 N),
// warp tile 32x64 via mma.sync.m16n8k8.row.col.f32.tf32.tf32.f32.

__device__ __forceinline__ float to_tf32(float x) {
    float y;
    asm("cvt.rna.tf32.f32 %0, %1;" : "=f"(y) : "f"(x));
    return y;
}

__global__ __launch_bounds__(256, 2)
void gemm_k(const float* __restrict__ Hext,
            const float* __restrict__ W, int K) {
    __shared__ float As[128 * SA];  // [row][k], k-chunk of 32
    __shared__ float Bs[32 * SB];   // [k][col]
    const float* H = Hext ? Hext : d_h;

    int tid  = threadIdx.x;
    int wid  = tid >> 5;
    int lane = tid & 31;
    int g    = lane >> 2;
    int tig  = lane & 3;
    int wm   = wid & 3;
    int wn   = wid >> 2;
    int m0   = blockIdx.x * 128;

    float acc[2][8][4];
    #pragma unroll
    for (int mt = 0; mt < 2; mt++)
        #pragma unroll
        for (int nf = 0; nf < 8; nf++)
            #pragma unroll
            for (int c = 0; c < 4; c++) acc[mt][nf][c] = 0.0f;

    int nkc = (K + 31) / 32;
    for (int kc = 0; kc < nkc; kc++) {
        int k0 = kc * 32;
        #pragma unroll
        for (int i = tid; i < 128 * 32; i += 256) {
            int r = i >> 5, kk = i & 31;
            int gm = m0 + r, gk = k0 + kk;
            float v = (gm < NN && gk < K) ? H[(size_t)gm * K + gk] : 0.0f;
            As[r * SA + kk] = to_tf32(v);
        }
        #pragma unroll
        for (int i = tid; i < 32 * 128; i += 256) {
            int kk = i >> 7, c = i & 127;
            int gk = k0 + kk;
            float v = (gk < K) ? W[gk * HD + c] : 0.0f;
            Bs[kk * SB + c] = to_tf32(v);
        }
        __syncthreads();

        #pragma unroll
        for (int ks = 0; ks < 4; ks++) {
            int kb = ks * 8;
            uint32_t a[2][4];
            #pragma unroll
            for (int mt = 0; mt < 2; mt++) {
                int rb = wm * 32 + mt * 16;
                a[mt][0] = __float_as_uint(As[(rb + g)     * SA + kb + tig]);
                a[mt][1] = __float_as_uint(As[(rb + g + 8) * SA + kb + tig]);
                a[mt][2] = __float_as_uint(As[(rb + g)     * SA + kb + tig + 4]);
                a[mt][3] = __float_as_uint(As[(rb + g + 8) * SA + kb + tig + 4]);
            }
            #pragma unroll
            for (int nf = 0; nf < 8; nf++) {
                int cb = wn * 64 + nf * 8 + g;
                uint32_t b0 = __float_as_uint(Bs[(kb + tig)     * SB + cb]);
                uint32_t b1 = __float_as_uint(Bs[(kb + tig + 4) * SB + cb]);
                #pragma unroll
                for (int mt = 0; mt < 2; mt++) {
                    asm volatile(
                        "mma.sync.aligned.m16n8k8.row.col.f32.tf32.tf32.f32 "
                        "{%0,%1,%2,%3}, {%4,%5,%6,%7}, {%8,%9}, {%0,%1,%2,%3};"
                        : "+f"(acc[mt][nf][0]), "+f"(acc[mt][nf][1]),
                          "+f"(acc[mt][nf][2]), "+f"(acc[mt][nf][3])
                        : "r"(a[mt][0]), "r"(a[mt][1]), "r"(a[mt][2]), "r"(a[mt][3]),
                          "r"(b0), "r"(b1));
                }
            }
        }
        __syncthreads();
    }

    #pragma unroll
    for (int mt = 0; mt < 2; mt++) {
        int r0 = m0 + wm * 32 + mt * 16 + g;
        int r1 = r0 + 8;
        float sc0 = (r0 < NN) ? d_dis[r0] : 0.0f;
        float sc1 = (r1 < NN) ? d_dis[r1] : 0.0f;
        #pragma unroll
        for (int nf = 0; nf < 8; nf++) {
            int col = wn * 64 + nf * 8 + 2 * tig;
            if (r0 < NN) {
                __half2 h = __floats2half2_rn(acc[mt][nf][0] * sc0,
                                              acc[mt][nf][1] * sc0);
                *(__half2*)&d_gh[(size_t)r0 * HD + col] = h;
            }
            if (r1 < NN) {
                __half2 h = __floats2half2_rn(acc[mt][nf][2] * sc1,
                                              acc[mt][nf][3] * sc1);
                *(__half2*)&d_gh[(size_t)r1 * HD + col] = h;
            }
        }
    }
}

// ---------------- per-layer aggregation + bias + tanh ----------------
// one warp per node; TWO half-warps process two edges at once.
// Each of 16 lanes per half owns 16B (uint4 = 8 halves) of the 256B row,
// so each gather is an LDG.128 (512B per warp instruction, 2 rows).
// Batch 4 pairs -> 8 edges (2KB) in flight per warp.

__device__ __forceinline__ void add8(float* acc, uint4 r) {
    const __half2* hp = (const __half2*)&r;
    #pragma unroll
    for (int q = 0; q < 4; q++) {
        float2 v = __half22float2(hp[q]);
        acc[2 * q]     += v.x;
        acc[2 * q + 1] += v.y;
    }
}

__global__ void agg_k(const float* __restrict__ bias,
                      float* __restrict__ outp) {
    int gw = (blockIdx.x * blockDim.x + threadIdx.x) >> 5;
    int lane = threadIdx.x & 31;
    if (gw >= NN) return;
    float* out = outp ? outp : d_h;

    int half = lane >> 4;   // 0/1: which edge of the pair
    int sub  = lane & 15;   // owns halves [sub*8, sub*8+8)
    const uint4* gh = (const uint4*)d_gh;   // 16B units, 16 per row
    const uint4 Z = make_uint4(0, 0, 0, 0);

    int n = gw;
    float acc[8];
    #pragma unroll
    for (int q = 0; q < 8; q++) acc[q] = 0.0f;
    if (half == 0) add8(acc, gh[(size_t)n * 16 + sub]);   // self term

    int lo = d_rowptr[n];
    int hi = d_rowptr[n + 1];
    for (int base = lo; base < hi; base += 32) {
        int idx = base + lane;
        int myc = (idx < hi) ? __ldg(&d_col[idx]) : -1;
        int cnt = hi - base; if (cnt > 32) cnt = 32;
        int npair = (cnt + 1) >> 1;
        int p = 0;
        for (; p + 4 <= npair; p += 4) {
            int s0 = __shfl_sync(0xffffffffu, myc, 2 * (p + 0) + half);
            int s1 = __shfl_sync(0xffffffffu, myc, 2 * (p + 1) + half);
            int s2 = __shfl_sync(0xffffffffu, myc, 2 * (p + 2) + half);
            int s3 = __shfl_sync(0xffffffffu, myc, 2 * (p + 3) + half);
            uint4 r0 = (s0 >= 0) ? __ldg(&gh[(size_t)s0 * 16 + sub]) : Z;
            uint4 r1 = (s1 >= 0) ? __ldg(&gh[(size_t)s1 * 16 + sub]) : Z;
            uint4 r2 = (s2 >= 0) ? __ldg(&gh[(size_t)s2 * 16 + sub]) : Z;
            uint4 r3 = (s3 >= 0) ? __ldg(&gh[(size_t)s3 * 16 + sub]) : Z;
            add8(acc, r0);
            add8(acc, r1);
            add8(acc, r2);
            add8(acc, r3);
        }
        for (; p < npair; p++) {
            int s = __shfl_sync(0xffffffffu, myc, 2 * p + half);
            uint4 r = (s >= 0) ? __ldg(&gh[(size_t)s * 16 + sub]) : Z;
            add8(acc, r);
        }
    }

    // combine the two half-warps
    #pragma unroll
    for (int q = 0; q < 8; q++)
        acc[q] += __shfl_xor_sync(0xffffffffu, acc[q], 16);

    if (half == 0) {
        float sc = d_dis[n];
        float4 b0 = *(const float4*)&bias[sub * 8];
        float4 b1 = *(const float4*)&bias[sub * 8 + 4];
        float4 o0, o1;
        o0.x = tanhf(sc * acc[0] + b0.x);
        o0.y = tanhf(sc * acc[1] + b0.y);
        o0.z = tanhf(sc * acc[2] + b0.z);
        o0.w = tanhf(sc * acc[3] + b0.w);
        o1.x = tanhf(sc * acc[4] + b1.x);
        o1.y = tanhf(sc * acc[5] + b1.y);
        o1.z = tanhf(sc * acc[6] + b1.z);
        o1.w = tanhf(sc * acc[7] + b1.w);
        *(float4*)&out[(size_t)n * HD + sub * 8]     = o0;
        *(float4*)&out[(size_t)n * HD + sub * 8 + 4] = o1;
    }
}

// ---------------- launch ----------------

extern "C" void kernel_launch(void* const* d_in, const int* in_sizes, int n_in,
                              void* d_out, int out_size) {
    const float* x  = (const float*)d_in[0];   // [NN, 133]
    const int*   ei = (const int*)d_in[1];     // [2, NE] int32
    const float* W[4] = {(const float*)d_in[2], (const float*)d_in[4],
                         (const float*)d_in[6], (const float*)d_in[8]};
    const float* B[4] = {(const float*)d_in[3], (const float*)d_in[5],
                         (const float*)d_in[7], (const float*)d_in[9]};
    float* out = (float*)d_out;

    zero_cnt_k<<<(NN + 255) / 256, 256>>>();
    count_k<<<(NE + 255) / 256, 256>>>(ei);
    scan_k<<<1, 1024>>>();
    fill_k<<<(NE + 255) / 256, 256>>>(ei);

    const int GEMM_BLOCKS = (NN + 127) / 128;
    const int AGG_BLOCKS  = (NN * 32 + 255) / 256;

    gemm_k<<<GEMM_BLOCKS, 256>>>(x, W[0], NF);
    agg_k<<<AGG_BLOCKS, 256>>>(B[0], nullptr);
    gemm_k<<<GEMM_BLOCKS, 256>>>(nullptr, W[1], HD);
    agg_k<<<AGG_BLOCKS, 256>>>(B[1], nullptr);
    gemm_k<<<GEMM_BLOCKS, 256>>>(nullptr, W[2], HD);
    agg_k<<<AGG_BLOCKS, 256>>>(B[2], nullptr);
    gemm_k<<<GEMM_BLOCKS, 256>>>(nullptr, W[3], HD);
    agg_k<<<AGG_BLOCKS, 256>>>(B[3], out);
}

// round 14
// speedup vs baseline: 1.0405x; 1.0405x over previous
#include <cuda_runtime.h>
#include <cuda_fp16.h>
#include <math.h>
#include <stdint.h>

#define NN 100000
#define NE 1600000
#define NF 133
#define HD 128
#define SA 36    // As row stride (floats): %32==4 -> conflict-free A frag reads
#define SB 136   // Bs row stride (floats): %32==8 -> conflict-free B frag reads

// ---- scratch (device globals) ----
__device__ __half d_gh[NN * HD];   // g = dis[n]*(h@W)[n], fp16 for gather bandwidth
__device__ float d_h[NN * HD];     // hidden activations between layers (fp32)
__device__ int   d_cnt[NN];
__device__ int   d_rowptr[NN + 1];
__device__ int   d_head[NN];
__device__ int   d_col[NE];
__device__ float d_dis[NN];

// ---------------- preprocessing ----------------

__global__ void zero_cnt_k() {
    int i = blockIdx.x * blockDim.x + threadIdx.x;
    if (i < NN) d_cnt[i] = 0;
}

__global__ void count_k(const int* __restrict__ ei) {
    int e = (blockIdx.x * blockDim.x + threadIdx.x) * 4;
    if (e < NE) {   // NE % 4 == 0
        int4 d = *(const int4*)&ei[NE + e];
        atomicAdd(&d_cnt[d.x], 1);
        atomicAdd(&d_cnt[d.y], 1);
        atomicAdd(&d_cnt[d.z], 1);
        atomicAdd(&d_cnt[d.w], 1);
    }
}

__global__ void scan_k() {
    __shared__ int sums[1024];
    int t = threadIdx.x;
    const int CH = (NN + 1023) / 1024;
    int lo = t * CH;
    int hi = lo + CH; if (hi > NN) hi = NN;
    int s = 0;
    for (int i = lo; i < hi; i++) s += d_cnt[i];
    sums[t] = s;
    __syncthreads();
    for (int off = 1; off < 1024; off <<= 1) {
        int v = 0;
        if (t >= off) v = sums[t - off];
        __syncthreads();
        sums[t] += v;
        __syncthreads();
    }
    int run = sums[t] - s;
    for (int i = lo; i < hi; i++) {
        int c = d_cnt[i];
        d_rowptr[i] = run;
        d_head[i]   = run;
        d_dis[i]    = rsqrtf((float)c + 1.0f);
        run += c;
    }
    if (t == 1023) d_rowptr[NN] = run;
}

__global__ void fill_k(const int* __restrict__ ei) {
    int e = (blockIdx.x * blockDim.x + threadIdx.x) * 2;
    if (e < NE) {   // NE % 2 == 0
        int2 s = *(const int2*)&ei[e];
        int2 d = *(const int2*)&ei[NE + e];
        int p0 = atomicAdd(&d_head[d.x], 1);
        d_col[p0] = s.x;
        int p1 = atomicAdd(&d_head[d.y], 1);
        d_col[p1] = s.y;
    }
}

// ---------------- per-layer GEMM (tf32 tensor cores) ----------------
// g_fp16 = dis[m] * (H @ W).  Block tile 128x128, 8 warps (4 M x 2 N),
// warp tile 32x64 via mma.sync.m16n8k8.row.col.f32.tf32.tf32.f32.

__device__ __forceinline__ float to_tf32(float x) {
    float y;
    asm("cvt.rna.tf32.f32 %0, %1;" : "=f"(y) : "f"(x));
    return y;
}

__global__ __launch_bounds__(256, 2)
void gemm_k(const float* __restrict__ Hext,
            const float* __restrict__ W, int K) {
    __shared__ float As[128 * SA];  // [row][k], k-chunk of 32
    __shared__ float Bs[32 * SB];   // [k][col]
    const float* H = Hext ? Hext : d_h;

    int tid  = threadIdx.x;
    int wid  = tid >> 5;
    int lane = tid & 31;
    int g    = lane >> 2;
    int tig  = lane & 3;
    int wm   = wid & 3;
    int wn   = wid >> 2;
    int m0   = blockIdx.x * 128;

    float acc[2][8][4];
    #pragma unroll
    for (int mt = 0; mt < 2; mt++)
        #pragma unroll
        for (int nf = 0; nf < 8; nf++)
            #pragma unroll
            for (int c = 0; c < 4; c++) acc[mt][nf][c] = 0.0f;

    int nkc = (K + 31) / 32;
    for (int kc = 0; kc < nkc; kc++) {
        int k0 = kc * 32;
        #pragma unroll
        for (int i = tid; i < 128 * 32; i += 256) {
            int r = i >> 5, kk = i & 31;
            int gm = m0 + r, gk = k0 + kk;
            float v = (gm < NN && gk < K) ? H[(size_t)gm * K + gk] : 0.0f;
            As[r * SA + kk] = to_tf32(v);
        }
        #pragma unroll
        for (int i = tid; i < 32 * 128; i += 256) {
            int kk = i >> 7, c = i & 127;
            int gk = k0 + kk;
            float v = (gk < K) ? W[gk * HD + c] : 0.0f;
            Bs[kk * SB + c] = to_tf32(v);
        }
        __syncthreads();

        #pragma unroll
        for (int ks = 0; ks < 4; ks++) {
            int kb = ks * 8;
            uint32_t a[2][4];
            #pragma unroll
            for (int mt = 0; mt < 2; mt++) {
                int rb = wm * 32 + mt * 16;
                a[mt][0] = __float_as_uint(As[(rb + g)     * SA + kb + tig]);
                a[mt][1] = __float_as_uint(As[(rb + g + 8) * SA + kb + tig]);
                a[mt][2] = __float_as_uint(As[(rb + g)     * SA + kb + tig + 4]);
                a[mt][3] = __float_as_uint(As[(rb + g + 8) * SA + kb + tig + 4]);
            }
            #pragma unroll
            for (int nf = 0; nf < 8; nf++) {
                int cb = wn * 64 + nf * 8 + g;
                uint32_t b0 = __float_as_uint(Bs[(kb + tig)     * SB + cb]);
                uint32_t b1 = __float_as_uint(Bs[(kb + tig + 4) * SB + cb]);
                #pragma unroll
                for (int mt = 0; mt < 2; mt++) {
                    asm volatile(
                        "mma.sync.aligned.m16n8k8.row.col.f32.tf32.tf32.f32 "
                        "{%0,%1,%2,%3}, {%4,%5,%6,%7}, {%8,%9}, {%0,%1,%2,%3};"
                        : "+f"(acc[mt][nf][0]), "+f"(acc[mt][nf][1]),
                          "+f"(acc[mt][nf][2]), "+f"(acc[mt][nf][3])
                        : "r"(a[mt][0]), "r"(a[mt][1]), "r"(a[mt][2]), "r"(a[mt][3]),
                          "r"(b0), "r"(b1));
                }
            }
        }
        __syncthreads();
    }

    #pragma unroll
    for (int mt = 0; mt < 2; mt++) {
        int r0 = m0 + wm * 32 + mt * 16 + g;
        int r1 = r0 + 8;
        float sc0 = (r0 < NN) ? d_dis[r0] : 0.0f;
        float sc1 = (r1 < NN) ? d_dis[r1] : 0.0f;
        #pragma unroll
        for (int nf = 0; nf < 8; nf++) {
            int col = wn * 64 + nf * 8 + 2 * tig;
            if (r0 < NN) {
                __half2 h = __floats2half2_rn(acc[mt][nf][0] * sc0,
                                              acc[mt][nf][1] * sc0);
                *(__half2*)&d_gh[(size_t)r0 * HD + col] = h;
            }
            if (r1 < NN) {
                __half2 h = __floats2half2_rn(acc[mt][nf][2] * sc1,
                                              acc[mt][nf][3] * sc1);
                *(__half2*)&d_gh[(size_t)r1 * HD + col] = h;
            }
        }
    }
}

// ---------------- per-layer aggregation + bias + tanh ----------------
// ONE WARP handles TWO adjacent nodes (NN even). Per-edge shape identical
// to R12 (32-lane LDG.64 row reads, same fp add order per node), but node
// A's and node B's 4-deep batches are issued back-to-back: 8 independent
// LDG.64 in flight per warp (2KB) before any consume.

__global__ void agg_k(const float* __restrict__ bias,
                      float* __restrict__ outp) {
    int gw = (blockIdx.x * blockDim.x + threadIdx.x) >> 5;
    int lane = threadIdx.x & 31;
    if (gw >= NN / 2) return;
    float* out = outp ? outp : d_h;

    const uint2* gh = (const uint2*)d_gh;   // 8B units, 32 per row
    const uint2 Z2 = make_uint2(0u, 0u);
    int nA = gw * 2;
    int nB = nA + 1;

    float2 accA0, accA1, accB0, accB1;
    {   // self terms
        uint2 rA = gh[(size_t)nA * 32 + lane];
        accA0 = __half22float2(*(const __half2*)&rA.x);
        accA1 = __half22float2(*(const __half2*)&rA.y);
        uint2 rB = gh[(size_t)nB * 32 + lane];
        accB0 = __half22float2(*(const __half2*)&rB.x);
        accB1 = __half22float2(*(const __half2*)&rB.y);
    }

    int baseA = d_rowptr[nA];
    int hiA   = d_rowptr[nA + 1];
    int baseB = hiA;                 // rowptr[nB] == rowptr[nA+1]
    int hiB   = d_rowptr[nB + 1];

    while (baseA < hiA || baseB < hiB) {
        int iA = baseA + lane, iB = baseB + lane;
        int mycA = (iA < hiA) ? __ldg(&d_col[iA]) : -1;
        int mycB = (iB < hiB) ? __ldg(&d_col[iB]) : -1;
        int cntA = hiA - baseA; cntA = cntA < 0 ? 0 : (cntA > 32 ? 32 : cntA);
        int cntB = hiB - baseB; cntB = cntB < 0 ? 0 : (cntB > 32 ? 32 : cntB);
        int mx = cntA > cntB ? cntA : cntB;
        for (int j = 0; j < mx; j += 4) {   // j+3 <= 31 always (mx <= 32)
            int sA0 = __shfl_sync(0xffffffffu, mycA, j);
            int sA1 = __shfl_sync(0xffffffffu, mycA, j + 1);
            int sA2 = __shfl_sync(0xffffffffu, mycA, j + 2);
            int sA3 = __shfl_sync(0xffffffffu, mycA, j + 3);
            int sB0 = __shfl_sync(0xffffffffu, mycB, j);
            int sB1 = __shfl_sync(0xffffffffu, mycB, j + 1);
            int sB2 = __shfl_sync(0xffffffffu, mycB, j + 2);
            int sB3 = __shfl_sync(0xffffffffu, mycB, j + 3);
            uint2 rA0 = (sA0 >= 0) ? __ldg(&gh[(size_t)sA0 * 32 + lane]) : Z2;
            uint2 rA1 = (sA1 >= 0) ? __ldg(&gh[(size_t)sA1 * 32 + lane]) : Z2;
            uint2 rA2 = (sA2 >= 0) ? __ldg(&gh[(size_t)sA2 * 32 + lane]) : Z2;
            uint2 rA3 = (sA3 >= 0) ? __ldg(&gh[(size_t)sA3 * 32 + lane]) : Z2;
            uint2 rB0 = (sB0 >= 0) ? __ldg(&gh[(size_t)sB0 * 32 + lane]) : Z2;
            uint2 rB1 = (sB1 >= 0) ? __ldg(&gh[(size_t)sB1 * 32 + lane]) : Z2;
            uint2 rB2 = (sB2 >= 0) ? __ldg(&gh[(size_t)sB2 * 32 + lane]) : Z2;
            uint2 rB3 = (sB3 >= 0) ? __ldg(&gh[(size_t)sB3 * 32 + lane]) : Z2;
            float2 v;
            v = __half22float2(*(const __half2*)&rA0.x); accA0.x += v.x; accA0.y += v.y;
            v = __half22float2(*(const __half2*)&rA0.y); accA1.x += v.x; accA1.y += v.y;
            v = __half22float2(*(const __half2*)&rA1.x); accA0.x += v.x; accA0.y += v.y;
            v = __half22float2(*(const __half2*)&rA1.y); accA1.x += v.x; accA1.y += v.y;
            v = __half22float2(*(const __half2*)&rA2.x); accA0.x += v.x; accA0.y += v.y;
            v = __half22float2(*(const __half2*)&rA2.y); accA1.x += v.x; accA1.y += v.y;
            v = __half22float2(*(const __half2*)&rA3.x); accA0.x += v.x; accA0.y += v.y;
            v = __half22float2(*(const __half2*)&rA3.y); accA1.x += v.x; accA1.y += v.y;
            v = __half22float2(*(const __half2*)&rB0.x); accB0.x += v.x; accB0.y += v.y;
            v = __half22float2(*(const __half2*)&rB0.y); accB1.x += v.x; accB1.y += v.y;
            v = __half22float2(*(const __half2*)&rB1.x); accB0.x += v.x; accB0.y += v.y;
            v = __half22float2(*(const __half2*)&rB1.y); accB1.x += v.x; accB1.y += v.y;
            v = __half22float2(*(const __half2*)&rB2.x); accB0.x += v.x; accB0.y += v.y;
            v = __half22float2(*(const __half2*)&rB2.y); accB1.x += v.x; accB1.y += v.y;
            v = __half22float2(*(const __half2*)&rB3.x); accB0.x += v.x; accB0.y += v.y;
            v = __half22float2(*(const __half2*)&rB3.y); accB1.x += v.x; accB1.y += v.y;
        }
        baseA += 32; baseB += 32;
    }

    float4 b = *(const float4*)&bias[lane * 4];
    {
        float sc = d_dis[nA];
        float4 o;
        o.x = tanhf(sc * accA0.x + b.x);
        o.y = tanhf(sc * accA0.y + b.y);
        o.z = tanhf(sc * accA1.x + b.z);
        o.w = tanhf(sc * accA1.y + b.w);
        *(float4*)&out[(size_t)nA * HD + lane * 4] = o;
    }
    {
        float sc = d_dis[nB];
        float4 o;
        o.x = tanhf(sc * accB0.x + b.x);
        o.y = tanhf(sc * accB0.y + b.y);
        o.z = tanhf(sc * accB1.x + b.z);
        o.w = tanhf(sc * accB1.y + b.w);
        *(float4*)&out[(size_t)nB * HD + lane * 4] = o;
    }
}

// ---------------- launch ----------------

extern "C" void kernel_launch(void* const* d_in, const int* in_sizes, int n_in,
                              void* d_out, int out_size) {
    const float* x  = (const float*)d_in[0];   // [NN, 133]
    const int*   ei = (const int*)d_in[1];     // [2, NE] int32
    const float* W[4] = {(const float*)d_in[2], (const float*)d_in[4],
                         (const float*)d_in[6], (const float*)d_in[8]};
    const float* B[4] = {(const float*)d_in[3], (const float*)d_in[5],
                         (const float*)d_in[7], (const float*)d_in[9]};
    float* out = (float*)d_out;

    zero_cnt_k<<<(NN + 255) / 256, 256>>>();
    count_k<<<(NE / 4 + 255) / 256, 256>>>(ei);
    scan_k<<<1, 1024>>>();
    fill_k<<<(NE / 2 + 255) / 256, 256>>>(ei);

    const int GEMM_BLOCKS = (NN + 127) / 128;
    const int AGG_BLOCKS  = ((NN / 2) * 32 + 255) / 256;

    gemm_k<<<GEMM_BLOCKS, 256>>>(x, W[0], NF);
    agg_k<<<AGG_BLOCKS, 256>>>(B[0], nullptr);
    gemm_k<<<GEMM_BLOCKS, 256>>>(nullptr, W[1], HD);
    agg_k<<<AGG_BLOCKS, 256>>>(B[1], nullptr);
    gemm_k<<<GEMM_BLOCKS, 256>>>(nullptr, W[2], HD);
    agg_k<<<AGG_BLOCKS, 256>>>(B[2], nullptr);
    gemm_k<<<GEMM_BLOCKS, 256>>>(nullptr, W[3], HD);
    agg_k<<<AGG_BLOCKS, 256>>>(B[3], out);
}